// round 3
// baseline (speedup 1.0000x reference)
#include <cuda_runtime.h>
#include <cuda_fp16.h>

// Problem constants (fixed by the reference)
#define MM 8192   // B*S tokens
#define HH 4096   // hidden
#define II 11008  // intermediate
#define RR 1024   // SVD rank

// ---------------- scratch (device globals: no allocation allowed) ----------
__device__ __half g_xT[(size_t)HH * MM];     // x transposed, fp16  [H, M]
__device__ __half g_t_up[(size_t)RR * MM];   // [R, M]
__device__ __half g_t_gate[(size_t)RR * MM]; // [R, M]
__device__ __half g_t_down[(size_t)RR * MM]; // [R, M]
__device__ __half g_inter[(size_t)II * MM];  // SwiGLU output, [I, M]

// ---------------- transpose: x[M,H] f32 -> xT[H,M] f16 ---------------------
__global__ void k_transpose(const float* __restrict__ x, __half* __restrict__ xT) {
    __shared__ float tile[32][33];
    int h0 = blockIdx.x * 32;
    int m0 = blockIdx.y * 32;
    int tx = threadIdx.x, ty = threadIdx.y;
#pragma unroll
    for (int i = ty; i < 32; i += 8)
        tile[i][tx] = x[(size_t)(m0 + i) * HH + h0 + tx];
    __syncthreads();
#pragma unroll
    for (int i = ty; i < 32; i += 8)
        xT[(size_t)(h0 + i) * MM + m0 + tx] = __float2half_rn(tile[tx][i]);
}

// ---------------------------------------------------------------------------
// Core GEMM segment: acc[4][8] (o x m micro-tile) +=
//   A[o0..o0+64, k0..k0+K) (fp32, row-major, stride K)  X
//   B rows (fp16, row idx[k] or k, stride M), columns m0..m0+128
// Tile: BO=64, BM=128, BK=16, 256 threads, thread-tile 4(o) x 8(m).
// ---------------------------------------------------------------------------
__device__ __forceinline__ void gemm_seg(
    const float* __restrict__ A,
    const __half* __restrict__ Bsrc, const int* __restrict__ idx, int K,
    int o0, int m0, int tid,
    float (&acc)[4][8],
    float (*As)[68], float (*Bs)[128])
{
    const int tx = tid & 15, ty = tid >> 4;
    const int ka = tid & 15;        // A-load k
    const int oa = tid >> 4;        // A-load o base
    const int kb = tid >> 4;        // B-load k
    const int mb = (tid & 15) * 8;  // B-load m offset (8 halves = 16B)

    for (int k0 = 0; k0 < K; k0 += 16) {
        // load A tile (weights, k-contiguous): 4 rows per thread
        const float* Ap = A + (size_t)o0 * K + (k0 + ka);
#pragma unroll
        for (int j = 0; j < 4; j++)
            As[ka][oa + j * 16] = Ap[(size_t)(oa + j * 16) * K];

        // load B tile (fp16 activations, m-contiguous, optional row gather)
        int row = idx ? idx[k0 + kb] : (k0 + kb);
        const __half* bp = Bsrc + (size_t)row * MM + m0 + mb;
        float4 v = *reinterpret_cast<const float4*>(bp);  // 8 halves
        __half2* hv = reinterpret_cast<__half2*>(&v);
#pragma unroll
        for (int j = 0; j < 4; j++) {
            float2 f = __half22float2(hv[j]);
            Bs[kb][mb + 2 * j]     = f.x;
            Bs[kb][mb + 2 * j + 1] = f.y;
        }
        __syncthreads();

#pragma unroll
        for (int kk = 0; kk < 16; kk++) {
            float a[4], b[8];
            *reinterpret_cast<float4*>(a)     = *reinterpret_cast<const float4*>(&As[kk][ty * 4]);
            *reinterpret_cast<float4*>(b)     = *reinterpret_cast<const float4*>(&Bs[kk][tx * 8]);
            *reinterpret_cast<float4*>(b + 4) = *reinterpret_cast<const float4*>(&Bs[kk][tx * 8 + 4]);
#pragma unroll
            for (int i = 0; i < 4; i++)
#pragma unroll
                for (int j = 0; j < 8; j++)
                    acc[i][j] = fmaf(a[i], b[j], acc[i][j]);
        }
        __syncthreads();
    }
}

// -------- stage 1 / 3a: C[O,M] (fp16) = W[O,K] @ gathered fp16 rows --------
// grid: (O/64, M/128)  -> o fastest so the (small) weight matrix stays in L2
__global__ __launch_bounds__(256) void k_gemm_feat(
    const float* __restrict__ A, const __half* __restrict__ Bsrc,
    const int* __restrict__ idx, int K, __half* __restrict__ C)
{
    __shared__ float As[16][68];
    __shared__ float Bs[16][128];
    const int o0 = blockIdx.x * 64;
    const int m0 = blockIdx.y * 128;
    const int tid = threadIdx.x;
    float acc[4][8] = {};
    gemm_seg(A, Bsrc, idx, K, o0, m0, tid, acc, As, Bs);

    const int tx = tid & 15, ty = tid >> 4;
#pragma unroll
    for (int i = 0; i < 4; i++) {
        __half2 h[4];
#pragma unroll
        for (int j = 0; j < 4; j++)
            h[j] = __floats2half2_rn(acc[i][2 * j], acc[i][2 * j + 1]);
        *reinterpret_cast<uint4*>(&C[(size_t)(o0 + ty * 4 + i) * MM + m0 + tx * 8]) =
            *reinterpret_cast<uint4*>(h);
    }
}

// -------- stage 2: fused up+gate+SwiGLU -> g_inter[I, M] fp16 ---------------
// grid: (M/128, I/64) -> m fastest so activations (~96 MB) stay L2-resident
// while the 180 MB of weights stream exactly once.
__global__ __launch_bounds__(256) void k_gemm_swiglu(
    const float* __restrict__ up_u, const float* __restrict__ up_c,
    const float* __restrict__ gate_u, const float* __restrict__ gate_c,
    const int* __restrict__ col_up, const int* __restrict__ col_gate)
{
    __shared__ float As[16][68];
    __shared__ float Bs[16][128];
    const int m0 = blockIdx.x * 128;
    const int o0 = blockIdx.y * 64;
    const int tid = threadIdx.x;

    float au[4][8] = {};
    float ag[4][8] = {};
    gemm_seg(up_u,   g_t_up,   nullptr,  RR,   o0, m0, tid, au, As, Bs);
    gemm_seg(up_c,   g_xT,     col_up,   1024, o0, m0, tid, au, As, Bs);
    gemm_seg(gate_u, g_t_gate, nullptr,  RR,   o0, m0, tid, ag, As, Bs);
    gemm_seg(gate_c, g_xT,     col_gate, 1024, o0, m0, tid, ag, As, Bs);

    const int tx = tid & 15, ty = tid >> 4;
#pragma unroll
    for (int i = 0; i < 4; i++) {
        __half2 h[4];
#pragma unroll
        for (int j = 0; j < 8; j += 2) {
            float g0 = ag[i][j],     u0 = au[i][j];
            float g1 = ag[i][j + 1], u1 = au[i][j + 1];
            float v0 = u0 * g0 / (1.0f + __expf(-g0));   // u * silu(g)
            float v1 = u1 * g1 / (1.0f + __expf(-g1));
            h[j / 2] = __floats2half2_rn(v0, v1);
        }
        *reinterpret_cast<uint4*>(&g_inter[(size_t)(o0 + ty * 4 + i) * MM + m0 + tx * 8]) =
            *reinterpret_cast<uint4*>(h);
    }
}

// -------- stage 3b: out[M,H] f32 = t_down^T @ down_u^T + interT_cols^T @ down_c^T
// A-side = fp16 K-major activations (m contiguous), B-side = fp32 weights [H,K].
// Tile: BMm=64 (ty->m,4), BH=128 (tx->h,8), BK=16, 256 threads.
// grid: (M/64, H/128) -> m fastest; activations (~62 MB) L2-resident.
__global__ __launch_bounds__(256) void k_gemm_out(
    const float* __restrict__ down_u, const float* __restrict__ down_c,
    const int* __restrict__ col_down, float* __restrict__ out)
{
    __shared__ float As[16][68];    // [k][m], m in 64
    __shared__ float Bs[16][132];   // [k][h], h in 128
    const int m0 = blockIdx.x * 64;
    const int h0 = blockIdx.y * 128;
    const int tid = threadIdx.x;
    const int tx = tid & 15, ty = tid >> 4;
    float acc[4][8] = {};

    for (int seg = 0; seg < 2; seg++) {
        const __half* Asrc = (seg == 0) ? g_t_down : g_inter;
        const int*    idx  = (seg == 0) ? nullptr  : col_down;
        const float*  Bw   = (seg == 0) ? down_u   : down_c;
        const int     K    = (seg == 0) ? 1024     : 2816;

        const int ka = tid >> 4;        // A-load k
        const int ma = (tid & 15) * 4;  // A-load m offset (4 halves = 8B)
        const int kb = tid & 15;        // B-load k
        const int hb = tid >> 4;        // B-load h base

        for (int k0 = 0; k0 < K; k0 += 16) {
            int row = idx ? idx[k0 + ka] : (k0 + ka);
            const __half* ap = Asrc + (size_t)row * MM + m0 + ma;
            uint2 raw = *reinterpret_cast<const uint2*>(ap);
            __half2* hv = reinterpret_cast<__half2*>(&raw);
            float2 f0 = __half22float2(hv[0]);
            float2 f1 = __half22float2(hv[1]);
            As[ka][ma]     = f0.x; As[ka][ma + 1] = f0.y;
            As[ka][ma + 2] = f1.x; As[ka][ma + 3] = f1.y;

            const float* bp = Bw + (size_t)h0 * K + (k0 + kb);
#pragma unroll
            for (int j = 0; j < 8; j++)
                Bs[kb][hb + j * 16] = bp[(size_t)(hb + j * 16) * K];
            __syncthreads();

#pragma unroll
            for (int kk = 0; kk < 16; kk++) {
                float a[4], b[8];
                *reinterpret_cast<float4*>(a)     = *reinterpret_cast<const float4*>(&As[kk][ty * 4]);
                *reinterpret_cast<float4*>(b)     = *reinterpret_cast<const float4*>(&Bs[kk][tx * 8]);
                *reinterpret_cast<float4*>(b + 4) = *reinterpret_cast<const float4*>(&Bs[kk][tx * 8 + 4]);
#pragma unroll
                for (int i = 0; i < 4; i++)
#pragma unroll
                    for (int j = 0; j < 8; j++)
                        acc[i][j] = fmaf(a[i], b[j], acc[i][j]);
            }
            __syncthreads();
        }
    }

#pragma unroll
    for (int i = 0; i < 4; i++) {
        float4 v0 = make_float4(acc[i][0], acc[i][1], acc[i][2], acc[i][3]);
        float4 v1 = make_float4(acc[i][4], acc[i][5], acc[i][6], acc[i][7]);
        float* dst = &out[(size_t)(m0 + ty * 4 + i) * HH + h0 + tx * 8];
        *reinterpret_cast<float4*>(dst)     = v0;
        *reinterpret_cast<float4*>(dst + 4) = v1;
    }
}

// ---------------------------------------------------------------------------
extern "C" void kernel_launch(void* const* d_in, const int* in_sizes, int n_in,
                              void* d_out, int out_size)
{
    const float* x       = (const float*)d_in[0];
    const float* up_v    = (const float*)d_in[1];
    const float* up_u    = (const float*)d_in[2];
    const float* up_c    = (const float*)d_in[3];
    const float* gate_v  = (const float*)d_in[4];
    const float* gate_u  = (const float*)d_in[5];
    const float* gate_c  = (const float*)d_in[6];
    const float* down_v  = (const float*)d_in[7];
    const float* down_u  = (const float*)d_in[8];
    const float* down_c  = (const float*)d_in[9];
    const int* svd_up    = (const int*)d_in[10];
    const int* col_up    = (const int*)d_in[11];
    const int* svd_gate  = (const int*)d_in[12];
    const int* col_gate  = (const int*)d_in[13];
    const int* svd_down  = (const int*)d_in[14];
    const int* col_down  = (const int*)d_in[15];
    float* out = (float*)d_out;

    __half *xT, *t_up, *t_gate, *t_down, *inter;
    cudaGetSymbolAddress((void**)&xT,     g_xT);
    cudaGetSymbolAddress((void**)&t_up,   g_t_up);
    cudaGetSymbolAddress((void**)&t_gate, g_t_gate);
    cudaGetSymbolAddress((void**)&t_down, g_t_down);
    cudaGetSymbolAddress((void**)&inter,  g_inter);

    // 1. xT = x^T (fp16)
    k_transpose<<<dim3(HH / 32, MM / 32), dim3(32, 8)>>>(x, xT);

    // 2. t_up / t_gate = Wv @ xT[svd rows]   (K = 3072)
    k_gemm_feat<<<dim3(RR / 64, MM / 128), 256>>>(up_v,   xT, svd_up,   3072, t_up);
    k_gemm_feat<<<dim3(RR / 64, MM / 128), 256>>>(gate_v, xT, svd_gate, 3072, t_gate);

    // 3. interT = silu(gate) * up  (fused dual GEMM)
    k_gemm_swiglu<<<dim3(MM / 128, II / 64), 256>>>(up_u, up_c, gate_u, gate_c,
                                                    col_up, col_gate);

    // 4. t_down = down_v @ interT[svd_down rows]   (K = 8192)
    k_gemm_feat<<<dim3(RR / 64, MM / 128), 256>>>(down_v, inter, svd_down, 8192, t_down);

    // 5. out[M,H] = down_u @ t_down + down_c @ interT[col_down rows]
    k_gemm_out<<<dim3(MM / 64, HH / 128), 256>>>(down_u, down_c, col_down, out);
}

// round 4
// speedup vs baseline: 1.0016x; 1.0016x over previous
#include <cuda_runtime.h>
#include <cuda_fp16.h>

// Problem constants (fixed by the reference)
#define MM 8192   // B*S tokens
#define HH 4096   // hidden
#define II 11008  // intermediate
#define RR 1024   // SVD rank

// ---------------- scratch (device globals: no allocation allowed) ----------
__device__ __half g_xT[(size_t)HH * MM];     // x transposed, fp16  [H, M]
__device__ __half g_t_up[(size_t)RR * MM];   // [R, M]
__device__ __half g_t_gate[(size_t)RR * MM]; // [R, M]
__device__ __half g_t_down[(size_t)RR * MM]; // [R, M]
__device__ __half g_inter[(size_t)II * MM];  // SwiGLU output, [I, M]

// ---------------- transpose: x[M,H] f32 -> xT[H,M] f16 ---------------------
__global__ void k_transpose(const float* __restrict__ x, __half* __restrict__ xT) {
    __shared__ float tile[32][33];
    int h0 = blockIdx.x * 32;
    int m0 = blockIdx.y * 32;
    int tx = threadIdx.x, ty = threadIdx.y;
#pragma unroll
    for (int i = ty; i < 32; i += 8)
        tile[i][tx] = x[(size_t)(m0 + i) * HH + h0 + tx];
    __syncthreads();
#pragma unroll
    for (int i = ty; i < 32; i += 8)
        xT[(size_t)(h0 + i) * MM + m0 + tx] = __float2half_rn(tile[tx][i]);
}

// ---------------------------------------------------------------------------
// Core GEMM segment: acc[4][8] (o x m micro-tile) +=
//   A[o0..o0+64, k0..k0+K) (fp32, row-major, stride K)  X
//   B rows (fp16, row idx[k] or k, stride M), columns m0..m0+128
// Tile: BO=64, BM=128, BK=16, 256 threads, thread-tile 4(o) x 8(m).
// ---------------------------------------------------------------------------
__device__ __forceinline__ void gemm_seg(
    const float* __restrict__ A,
    const __half* __restrict__ Bsrc, const int* __restrict__ idx, int K,
    int o0, int m0, int tid,
    float (&acc)[4][8],
    float (*As)[68], float (*Bs)[128])
{
    const int tx = tid & 15, ty = tid >> 4;
    const int ka = tid & 15;        // A-load k
    const int oa = tid >> 4;        // A-load o base
    const int kb = tid >> 4;        // B-load k
    const int mb = (tid & 15) * 8;  // B-load m offset (8 halves = 16B)

    for (int k0 = 0; k0 < K; k0 += 16) {
        // load A tile (weights, k-contiguous): 4 rows per thread
        const float* Ap = A + (size_t)o0 * K + (k0 + ka);
#pragma unroll
        for (int j = 0; j < 4; j++)
            As[ka][oa + j * 16] = Ap[(size_t)(oa + j * 16) * K];

        // load B tile (fp16 activations, m-contiguous, optional row gather)
        int row = idx ? idx[k0 + kb] : (k0 + kb);
        const __half* bp = Bsrc + (size_t)row * MM + m0 + mb;
        float4 v = *reinterpret_cast<const float4*>(bp);  // 8 halves
        __half2* hv = reinterpret_cast<__half2*>(&v);
#pragma unroll
        for (int j = 0; j < 4; j++) {
            float2 f = __half22float2(hv[j]);
            Bs[kb][mb + 2 * j]     = f.x;
            Bs[kb][mb + 2 * j + 1] = f.y;
        }
        __syncthreads();

#pragma unroll
        for (int kk = 0; kk < 16; kk++) {
            float a[4], b[8];
            *reinterpret_cast<float4*>(a)     = *reinterpret_cast<const float4*>(&As[kk][ty * 4]);
            *reinterpret_cast<float4*>(b)     = *reinterpret_cast<const float4*>(&Bs[kk][tx * 8]);
            *reinterpret_cast<float4*>(b + 4) = *reinterpret_cast<const float4*>(&Bs[kk][tx * 8 + 4]);
#pragma unroll
            for (int i = 0; i < 4; i++)
#pragma unroll
                for (int j = 0; j < 8; j++)
                    acc[i][j] = fmaf(a[i], b[j], acc[i][j]);
        }
        __syncthreads();
    }
}

// -------- stage 1 / 3a: C[O,M] (fp16) = W[O,K] @ gathered fp16 rows --------
// grid: (O/64, M/128)  -> o fastest so the (small) weight matrix stays in L2
__global__ __launch_bounds__(256) void k_gemm_feat(
    const float* __restrict__ A, const __half* __restrict__ Bsrc,
    const int* __restrict__ idx, int K, __half* __restrict__ C)
{
    __shared__ float As[16][68];
    __shared__ float Bs[16][128];
    const int o0 = blockIdx.x * 64;
    const int m0 = blockIdx.y * 128;
    const int tid = threadIdx.x;
    float acc[4][8] = {};
    gemm_seg(A, Bsrc, idx, K, o0, m0, tid, acc, As, Bs);

    const int tx = tid & 15, ty = tid >> 4;
#pragma unroll
    for (int i = 0; i < 4; i++) {
        __half2 h[4];
#pragma unroll
        for (int j = 0; j < 4; j++)
            h[j] = __floats2half2_rn(acc[i][2 * j], acc[i][2 * j + 1]);
        *reinterpret_cast<uint4*>(&C[(size_t)(o0 + ty * 4 + i) * MM + m0 + tx * 8]) =
            *reinterpret_cast<uint4*>(h);
    }
}

// -------- stage 2: fused up+gate+SwiGLU -> g_inter[I, M] fp16 ---------------
// grid: (M/128, I/64) -> m fastest so activations (~96 MB) stay L2-resident
// while the 180 MB of weights stream exactly once.
__global__ __launch_bounds__(256) void k_gemm_swiglu(
    const float* __restrict__ up_u, const float* __restrict__ up_c,
    const float* __restrict__ gate_u, const float* __restrict__ gate_c,
    const int* __restrict__ col_up, const int* __restrict__ col_gate)
{
    __shared__ float As[16][68];
    __shared__ float Bs[16][128];
    const int m0 = blockIdx.x * 128;
    const int o0 = blockIdx.y * 64;
    const int tid = threadIdx.x;

    float au[4][8] = {};
    float ag[4][8] = {};
    gemm_seg(up_u,   g_t_up,   nullptr,  RR,   o0, m0, tid, au, As, Bs);
    gemm_seg(up_c,   g_xT,     col_up,   1024, o0, m0, tid, au, As, Bs);
    gemm_seg(gate_u, g_t_gate, nullptr,  RR,   o0, m0, tid, ag, As, Bs);
    gemm_seg(gate_c, g_xT,     col_gate, 1024, o0, m0, tid, ag, As, Bs);

    const int tx = tid & 15, ty = tid >> 4;
#pragma unroll
    for (int i = 0; i < 4; i++) {
        __half2 h[4];
#pragma unroll
        for (int j = 0; j < 8; j += 2) {
            float g0 = ag[i][j],     u0 = au[i][j];
            float g1 = ag[i][j + 1], u1 = au[i][j + 1];
            float v0 = u0 * g0 / (1.0f + __expf(-g0));   // u * silu(g)
            float v1 = u1 * g1 / (1.0f + __expf(-g1));
            h[j / 2] = __floats2half2_rn(v0, v1);
        }
        *reinterpret_cast<uint4*>(&g_inter[(size_t)(o0 + ty * 4 + i) * MM + m0 + tx * 8]) =
            *reinterpret_cast<uint4*>(h);
    }
}

// -------- stage 3b: out[M,H] f32 = t_down^T @ down_u^T + interT_cols^T @ down_c^T
// A-side = fp16 K-major activations (m contiguous), B-side = fp32 weights [H,K].
// Tile: BMm=64 (ty->m,4), BH=128 (tx->h,8), BK=16, 256 threads.
// grid: (M/64, H/128) -> m fastest; activations (~62 MB) L2-resident.
__global__ __launch_bounds__(256) void k_gemm_out(
    const float* __restrict__ down_u, const float* __restrict__ down_c,
    const int* __restrict__ col_down, float* __restrict__ out)
{
    __shared__ float As[16][68];    // [k][m], m in 64
    __shared__ float Bs[16][132];   // [k][h], h in 128
    const int m0 = blockIdx.x * 64;
    const int h0 = blockIdx.y * 128;
    const int tid = threadIdx.x;
    const int tx = tid & 15, ty = tid >> 4;
    float acc[4][8] = {};

    for (int seg = 0; seg < 2; seg++) {
        const __half* Asrc = (seg == 0) ? g_t_down : g_inter;
        const int*    idx  = (seg == 0) ? nullptr  : col_down;
        const float*  Bw   = (seg == 0) ? down_u   : down_c;
        const int     K    = (seg == 0) ? 1024     : 2816;

        const int ka = tid >> 4;        // A-load k
        const int ma = (tid & 15) * 4;  // A-load m offset (4 halves = 8B)
        const int kb = tid & 15;        // B-load k
        const int hb = tid >> 4;        // B-load h base

        for (int k0 = 0; k0 < K; k0 += 16) {
            int row = idx ? idx[k0 + ka] : (k0 + ka);
            const __half* ap = Asrc + (size_t)row * MM + m0 + ma;
            uint2 raw = *reinterpret_cast<const uint2*>(ap);
            __half2* hv = reinterpret_cast<__half2*>(&raw);
            float2 f0 = __half22float2(hv[0]);
            float2 f1 = __half22float2(hv[1]);
            As[ka][ma]     = f0.x; As[ka][ma + 1] = f0.y;
            As[ka][ma + 2] = f1.x; As[ka][ma + 3] = f1.y;

            const float* bp = Bw + (size_t)h0 * K + (k0 + kb);
#pragma unroll
            for (int j = 0; j < 8; j++)
                Bs[kb][hb + j * 16] = bp[(size_t)(hb + j * 16) * K];
            __syncthreads();

#pragma unroll
            for (int kk = 0; kk < 16; kk++) {
                float a[4], b[8];
                *reinterpret_cast<float4*>(a)     = *reinterpret_cast<const float4*>(&As[kk][ty * 4]);
                *reinterpret_cast<float4*>(b)     = *reinterpret_cast<const float4*>(&Bs[kk][tx * 8]);
                *reinterpret_cast<float4*>(b + 4) = *reinterpret_cast<const float4*>(&Bs[kk][tx * 8 + 4]);
#pragma unroll
                for (int i = 0; i < 4; i++)
#pragma unroll
                    for (int j = 0; j < 8; j++)
                        acc[i][j] = fmaf(a[i], b[j], acc[i][j]);
            }
            __syncthreads();
        }
    }

#pragma unroll
    for (int i = 0; i < 4; i++) {
        float4 v0 = make_float4(acc[i][0], acc[i][1], acc[i][2], acc[i][3]);
        float4 v1 = make_float4(acc[i][4], acc[i][5], acc[i][6], acc[i][7]);
        float* dst = &out[(size_t)(m0 + ty * 4 + i) * HH + h0 + tx * 8];
        *reinterpret_cast<float4*>(dst)     = v0;
        *reinterpret_cast<float4*>(dst + 4) = v1;
    }
}

// ---------------------------------------------------------------------------
extern "C" void kernel_launch(void* const* d_in, const int* in_sizes, int n_in,
                              void* d_out, int out_size)
{
    const float* x       = (const float*)d_in[0];
    const float* up_v    = (const float*)d_in[1];
    const float* up_u    = (const float*)d_in[2];
    const float* up_c    = (const float*)d_in[3];
    const float* gate_v  = (const float*)d_in[4];
    const float* gate_u  = (const float*)d_in[5];
    const float* gate_c  = (const float*)d_in[6];
    const float* down_v  = (const float*)d_in[7];
    const float* down_u  = (const float*)d_in[8];
    const float* down_c  = (const float*)d_in[9];
    const int* svd_up    = (const int*)d_in[10];
    const int* col_up    = (const int*)d_in[11];
    const int* svd_gate  = (const int*)d_in[12];
    const int* col_gate  = (const int*)d_in[13];
    const int* svd_down  = (const int*)d_in[14];
    const int* col_down  = (const int*)d_in[15];
    float* out = (float*)d_out;

    __half *xT, *t_up, *t_gate, *t_down, *inter;
    cudaGetSymbolAddress((void**)&xT,     g_xT);
    cudaGetSymbolAddress((void**)&t_up,   g_t_up);
    cudaGetSymbolAddress((void**)&t_gate, g_t_gate);
    cudaGetSymbolAddress((void**)&t_down, g_t_down);
    cudaGetSymbolAddress((void**)&inter,  g_inter);

    // 1. xT = x^T (fp16)
    k_transpose<<<dim3(HH / 32, MM / 32), dim3(32, 8)>>>(x, xT);

    // 2. t_up / t_gate = Wv @ xT[svd rows]   (K = 3072)
    k_gemm_feat<<<dim3(RR / 64, MM / 128), 256>>>(up_v,   xT, svd_up,   3072, t_up);
    k_gemm_feat<<<dim3(RR / 64, MM / 128), 256>>>(gate_v, xT, svd_gate, 3072, t_gate);

    // 3. interT = silu(gate) * up  (fused dual GEMM)
    k_gemm_swiglu<<<dim3(MM / 128, II / 64), 256>>>(up_u, up_c, gate_u, gate_c,
                                                    col_up, col_gate);

    // 4. t_down = down_v @ interT[svd_down rows]   (K = 8192)
    k_gemm_feat<<<dim3(RR / 64, MM / 128), 256>>>(down_v, inter, svd_down, 8192, t_down);

    // 5. out[M,H] = down_u @ t_down + down_c @ interT[col_down rows]
    k_gemm_out<<<dim3(MM / 64, HH / 128), 256>>>(down_u, down_c, col_down, out);
}